// round 1
// baseline (speedup 1.0000x reference)
#include <cuda_runtime.h>
#include <cuda_bf16.h>
#include <math_constants.h>

// ---------------- problem dims ----------------
#define BB 8
#define NN 512
#define CC 512
#define EE 64
#define HH 16
#define DD 32
#define SCALE 0.17677669529663687f   // 1/sqrt(32)

#define NODE_OUT_ELEMS (BB*NN*CC)              // 2,097,152

// ---------------- scratch (static device memory; no allocs) ----------------
__device__ float g_qkv[(size_t)BB*NN*3*CC];            // [b*n][1536]  (q|k|v)
__device__ float g_S[(size_t)BB*HH*NN*NN];             // scores -> softmax a
__device__ float g_W[(size_t)BB*NN*EE];                // edge-weighted reduction [b,n,e]
__device__ float g_tmp[(size_t)BB*NN*CC];              // node accumulator

// =====================================================================
// Generic fp32 GEMM: C[M,Nn] = A[M,K] @ W[Nn,K]^T + bias
// BM=128, BN=128, BK=16, 256 threads, 8x8 per thread.
// M, Nn multiples of 128; K multiple of 16.
// =====================================================================
__global__ __launch_bounds__(256) void k_gemm(
    const float* __restrict__ A, const float* __restrict__ Wt,
    const float* __restrict__ bias, float* __restrict__ Cout,
    int M, int Nn, int K)
{
    __shared__ __align__(16) float As[16][128];
    __shared__ __align__(16) float Bs[16][128];

    const int bm = blockIdx.y * 128;
    const int bn = blockIdx.x * 128;
    const int tid = threadIdx.x;
    const int tx = tid & 15;       // col group
    const int ty = tid >> 4;       // row group

    float acc[8][8];
#pragma unroll
    for (int i = 0; i < 8; i++)
#pragma unroll
        for (int j = 0; j < 8; j++) acc[i][j] = 0.f;

    for (int k0 = 0; k0 < K; k0 += 16) {
        // A tile: 128 rows x 16 k  (512 float4 loads, 2 per thread)
#pragma unroll
        for (int l = tid; l < 512; l += 256) {
            int row = l >> 2;
            int kg  = (l & 3) * 4;
            float4 v = *(const float4*)&A[(size_t)(bm + row) * K + k0 + kg];
            As[kg+0][row] = v.x; As[kg+1][row] = v.y;
            As[kg+2][row] = v.z; As[kg+3][row] = v.w;
        }
        // W tile: 128 cols x 16 k
#pragma unroll
        for (int l = tid; l < 512; l += 256) {
            int col = l >> 2;
            int kg  = (l & 3) * 4;
            float4 v = *(const float4*)&Wt[(size_t)(bn + col) * K + k0 + kg];
            Bs[kg+0][col] = v.x; Bs[kg+1][col] = v.y;
            Bs[kg+2][col] = v.z; Bs[kg+3][col] = v.w;
        }
        __syncthreads();

#pragma unroll
        for (int kk = 0; kk < 16; kk++) {
            float a[8], b[8];
            *(float4*)&a[0] = *(const float4*)&As[kk][ty*8];
            *(float4*)&a[4] = *(const float4*)&As[kk][ty*8+4];
            *(float4*)&b[0] = *(const float4*)&Bs[kk][tx*8];
            *(float4*)&b[4] = *(const float4*)&Bs[kk][tx*8+4];
#pragma unroll
            for (int i = 0; i < 8; i++)
#pragma unroll
                for (int j = 0; j < 8; j++)
                    acc[i][j] += a[i] * b[j];
        }
        __syncthreads();
    }

#pragma unroll
    for (int i = 0; i < 8; i++) {
        int r = bm + ty*8 + i;
#pragma unroll
        for (int j = 0; j < 8; j++) {
            int c = bn + tx*8 + j;
            Cout[(size_t)r * Nn + c] = acc[i][j] + bias[c];
        }
    }
}

// =====================================================================
// Scores: S[b,h,n,m] = SCALE * sum_d q[b,h,n,d]*k[b,h,m,d]
// q,k live inside g_qkv: q col = h*32+d, k col = 512+h*32+d.
// grid (m_tiles=8, n_tiles=8, bh=128), 256 threads, 64x64 tile, 4x4/thread.
// =====================================================================
__global__ __launch_bounds__(256) void k_scores(
    const float* __restrict__ qkv, float* __restrict__ S)
{
    __shared__ __align__(16) float Qs[32][68];
    __shared__ __align__(16) float Ks[32][68];

    const int bh = blockIdx.z;
    const int b  = bh >> 4;
    const int h  = bh & 15;
    const int n0 = blockIdx.y * 64;
    const int m0 = blockIdx.x * 64;
    const int tid = threadIdx.x;

    const float* qbase = qkv + (size_t)b*NN*1536 + h*DD;
    const float* kbase = qkv + (size_t)b*NN*1536 + 512 + h*DD;

    // 64 rows x 32 d = 512 float4, 2 per thread
#pragma unroll
    for (int l = tid; l < 512; l += 256) {
        int row = l >> 3;
        int dg  = (l & 7) * 4;
        float4 v = *(const float4*)&qbase[(size_t)(n0+row)*1536 + dg];
        Qs[dg+0][row] = v.x; Qs[dg+1][row] = v.y;
        Qs[dg+2][row] = v.z; Qs[dg+3][row] = v.w;
    }
#pragma unroll
    for (int l = tid; l < 512; l += 256) {
        int row = l >> 3;
        int dg  = (l & 7) * 4;
        float4 v = *(const float4*)&kbase[(size_t)(m0+row)*1536 + dg];
        Ks[dg+0][row] = v.x; Ks[dg+1][row] = v.y;
        Ks[dg+2][row] = v.z; Ks[dg+3][row] = v.w;
    }
    __syncthreads();

    const int tx = tid & 15;
    const int ty = tid >> 4;
    float acc[4][4];
#pragma unroll
    for (int i = 0; i < 4; i++)
#pragma unroll
        for (int j = 0; j < 4; j++) acc[i][j] = 0.f;

#pragma unroll
    for (int d = 0; d < 32; d++) {
        float4 qa = *(const float4*)&Qs[d][ty*4];
        float4 kb = *(const float4*)&Ks[d][tx*4];
        float a[4] = {qa.x, qa.y, qa.z, qa.w};
        float c[4] = {kb.x, kb.y, kb.z, kb.w};
#pragma unroll
        for (int i = 0; i < 4; i++)
#pragma unroll
            for (int j = 0; j < 4; j++)
                acc[i][j] += a[i] * c[j];
    }

#pragma unroll
    for (int i = 0; i < 4; i++) {
        size_t row = (size_t)bh*NN + n0 + ty*4 + i;
#pragma unroll
        for (int j = 0; j < 4; j++)
            S[row*NN + m0 + tx*4 + j] = acc[i][j] * SCALE;
    }
}

// =====================================================================
// Fused per-(b,n): edge bias + attn softmax + residual + edge expand +
// edge softmax-weighted reduction. 512 threads = 16 warps.
// Writes: a -> S (overwrite), edge_out -> d_out tail, w -> g_W.
// =====================================================================
__global__ __launch_bounds__(512) void k_fused(
    const float* __restrict__ edge, const unsigned char* __restrict__ mask,
    const float* __restrict__ reduce_w, const float* __restrict__ reduce_b,
    const float* __restrict__ expand_w, const float* __restrict__ expand_b,
    float* __restrict__ S, float* __restrict__ edge_out, float* __restrict__ Wg)
{
    __shared__ __align__(16) float t_s[16][512];   // attn -> (a + attn)
    __shared__ __align__(16) float rw_s[64*16];    // [e][h] transposed reduce_w
    __shared__ __align__(16) float ew_s[64*16];    // [e][h] expand_w (native)
    __shared__ float eb_s[64];
    __shared__ float rb_s[16];
    __shared__ unsigned char mask_s[512];

    const int b = blockIdx.y;
    const int n = blockIdx.x;
    const int tid  = threadIdx.x;
    const int lane = tid & 31;
    const int warp = tid >> 5;

    for (int i = tid; i < 1024; i += 512) {
        int e = i >> 4, h = i & 15;
        rw_s[i] = reduce_w[h*EE + e];
        ew_s[i] = expand_w[i];
    }
    if (tid < 64) eb_s[tid] = expand_b[tid];
    if (tid < 16) rb_s[tid] = reduce_b[tid];
    mask_s[tid] = mask[b*NN + tid];
    __syncthreads();

    // ---------- phase 1: bias + scores -> t_s ----------
    {
        const int m = tid;
        float acc[16];
#pragma unroll
        for (int h = 0; h < 16; h++) acc[h] = rb_s[h];

        const size_t ebase = (size_t)b*EE*NN*NN + (size_t)n*NN + m;
#pragma unroll 4
        for (int e = 0; e < 64; e++) {
            float v = edge[ebase + (size_t)e*NN*NN];
            const float4* r4 = (const float4*)&rw_s[e*16];
            float4 r0 = r4[0], r1 = r4[1], r2 = r4[2], r3 = r4[3];
            acc[0]  += v*r0.x; acc[1]  += v*r0.y; acc[2]  += v*r0.z; acc[3]  += v*r0.w;
            acc[4]  += v*r1.x; acc[5]  += v*r1.y; acc[6]  += v*r1.z; acc[7]  += v*r1.w;
            acc[8]  += v*r2.x; acc[9]  += v*r2.y; acc[10] += v*r2.z; acc[11] += v*r2.w;
            acc[12] += v*r3.x; acc[13] += v*r3.y; acc[14] += v*r3.z; acc[15] += v*r3.w;
        }
        const size_t sidx = (size_t)(b*HH)*NN*NN + (size_t)n*NN + m;
#pragma unroll
        for (int h = 0; h < 16; h++)
            t_s[h][m] = acc[h] + S[sidx + (size_t)h*NN*NN];
    }
    __syncthreads();

    // ---------- phase 2: softmax per head (warp h handles head h) ----------
    {
        const int h = warp;
        float vals[16];
        float mx = -CUDART_INF_F;
#pragma unroll
        for (int i = 0; i < 16; i++) {
            int mm = lane + 32*i;
            vals[i] = t_s[h][mm];
            if (!mask_s[mm]) mx = fmaxf(mx, vals[i]);
        }
#pragma unroll
        for (int o = 16; o > 0; o >>= 1)
            mx = fmaxf(mx, __shfl_xor_sync(0xffffffffu, mx, o));

        float p[16];
        float sum = 0.f;
#pragma unroll
        for (int i = 0; i < 16; i++) {
            int mm = lane + 32*i;
            p[i] = mask_s[mm] ? 0.f : __expf(vals[i] - mx);
            sum += p[i];
        }
#pragma unroll
        for (int o = 16; o > 0; o >>= 1)
            sum += __shfl_xor_sync(0xffffffffu, sum, o);
        float inv = 1.f / sum;

        const size_t sbase = (size_t)(b*HH + h)*NN*NN + (size_t)n*NN;
#pragma unroll
        for (int i = 0; i < 16; i++) {
            int mm = lane + 32*i;
            float a = p[i] * inv;
            S[sbase + mm] = a;              // store softmax for a@v
            t_s[h][mm] = a + vals[i];       // residual for edge update
        }
    }
    __syncthreads();

    // ---------- phase 3: edge expand + edge softmax reduction ----------
    {
        const size_t eo_base = (size_t)b*EE*NN*NN + (size_t)n*NN;
#pragma unroll
        for (int j = 0; j < 4; j++) {
            int e = warp*4 + j;
            const float4* w4 = (const float4*)&ew_s[e*16];
            float4 w0 = w4[0], w1 = w4[1], w2 = w4[2], w3 = w4[3];
            float eb = eb_s[e];

            float vals[16];
            float mx = -CUDART_INF_F;
#pragma unroll
            for (int i = 0; i < 16; i++) {
                int mm = lane + 32*i;
                float s = eb;
                s += t_s[0][mm]*w0.x  + t_s[1][mm]*w0.y  + t_s[2][mm]*w0.z  + t_s[3][mm]*w0.w;
                s += t_s[4][mm]*w1.x  + t_s[5][mm]*w1.y  + t_s[6][mm]*w1.z  + t_s[7][mm]*w1.w;
                s += t_s[8][mm]*w2.x  + t_s[9][mm]*w2.y  + t_s[10][mm]*w2.z + t_s[11][mm]*w2.w;
                s += t_s[12][mm]*w3.x + t_s[13][mm]*w3.y + t_s[14][mm]*w3.z + t_s[15][mm]*w3.w;
                vals[i] = s;
                edge_out[eo_base + (size_t)e*NN*NN + mm] = s;
                if (!mask_s[mm]) mx = fmaxf(mx, s);
            }
#pragma unroll
            for (int o = 16; o > 0; o >>= 1)
                mx = fmaxf(mx, __shfl_xor_sync(0xffffffffu, mx, o));

            float sp = 0.f, spv = 0.f;
#pragma unroll
            for (int i = 0; i < 16; i++) {
                int mm = lane + 32*i;
                float pp = mask_s[mm] ? 0.f : __expf(vals[i] - mx);
                sp  += pp;
                spv += pp * vals[i];
            }
#pragma unroll
            for (int o = 16; o > 0; o >>= 1) {
                sp  += __shfl_xor_sync(0xffffffffu, sp,  o);
                spv += __shfl_xor_sync(0xffffffffu, spv, o);
            }
            if (lane == 0)
                Wg[((size_t)b*NN + n)*EE + e] = spv / sp;
        }
    }
}

// =====================================================================
// a @ v : g_tmp[b,n,h*32+d] = sum_m a[b,h,n,m] * v[b,m,h,d]
// grid (n_tiles=4, bh=128), 128 threads, 128x32 tile, 8x4/thread.
// =====================================================================
__global__ __launch_bounds__(128) void k_av(
    const float* __restrict__ S, const float* __restrict__ qkv,
    float* __restrict__ tmp)
{
    __shared__ __align__(16) float As[32][132];   // a^T: [m][n]
    __shared__ __align__(16) float Vs[32][36];    // [m][d]

    const int bh = blockIdx.y;
    const int b  = bh >> 4;
    const int h  = bh & 15;
    const int n0 = blockIdx.x * 128;
    const int tid = threadIdx.x;
    const int tx = tid & 7;     // d group (x4)
    const int ty = tid >> 3;    // n group (x8)

    const float* arow = S + ((size_t)bh*NN + n0)*NN;
    const float* vbase = qkv + (size_t)b*NN*1536 + 1024 + h*DD;

    float acc[8][4];
#pragma unroll
    for (int i = 0; i < 8; i++)
#pragma unroll
        for (int j = 0; j < 4; j++) acc[i][j] = 0.f;

    for (int mc = 0; mc < NN; mc += 32) {
        // a tile: 128 n x 32 m = 1024 float4, 8 per thread
#pragma unroll
        for (int l = tid; l < 1024; l += 128) {
            int row = l >> 3;
            int mg  = (l & 7) * 4;
            float4 v = *(const float4*)&arow[(size_t)row*NN + mc + mg];
            As[mg+0][row] = v.x; As[mg+1][row] = v.y;
            As[mg+2][row] = v.z; As[mg+3][row] = v.w;
        }
        // v tile: 32 m x 32 d = 256 float4, 2 per thread
#pragma unroll
        for (int l = tid; l < 256; l += 128) {
            int mm = l >> 3;
            int dg = (l & 7) * 4;
            float4 v = *(const float4*)&vbase[(size_t)(mc+mm)*1536 + dg];
            *(float4*)&Vs[mm][dg] = v;
        }
        __syncthreads();

#pragma unroll
        for (int mm = 0; mm < 32; mm++) {
            float a[8], bb[4];
            *(float4*)&a[0] = *(const float4*)&As[mm][ty*8];
            *(float4*)&a[4] = *(const float4*)&As[mm][ty*8+4];
            *(float4*)&bb[0] = *(const float4*)&Vs[mm][tx*4];
#pragma unroll
            for (int i = 0; i < 8; i++)
#pragma unroll
                for (int j = 0; j < 4; j++)
                    acc[i][j] += a[i] * bb[j];
        }
        __syncthreads();
    }

#pragma unroll
    for (int i = 0; i < 8; i++) {
        int nrow = n0 + ty*8 + i;
#pragma unroll
        for (int j = 0; j < 4; j++)
            tmp[((size_t)b*NN + nrow)*CC + h*DD + tx*4 + j] = acc[i][j];
    }
}

// =====================================================================
// x += w @ fc_w^T + fc_b  (K=64)
// =====================================================================
__global__ __launch_bounds__(256) void k_fc(
    const float* __restrict__ Wg, const float* __restrict__ fc_w,
    const float* __restrict__ fc_b, float* __restrict__ x)
{
    __shared__ float ws[64];
    const int bn = blockIdx.x;
    const int tid = threadIdx.x;
    if (tid < 64) ws[tid] = Wg[(size_t)bn*EE + tid];
    __syncthreads();

    for (int c = tid; c < CC; c += 256) {
        float s = fc_b[c];
        const float4* f4 = (const float4*)&fc_w[(size_t)c*EE];
#pragma unroll
        for (int e4 = 0; e4 < 16; e4++) {
            float4 f = f4[e4];
            s += ws[e4*4+0]*f.x + ws[e4*4+1]*f.y + ws[e4*4+2]*f.z + ws[e4*4+3]*f.w;
        }
        x[(size_t)bn*CC + c] += s;
    }
}

// =====================================================================
extern "C" void kernel_launch(void* const* d_in, const int* in_sizes, int n_in,
                              void* d_out, int out_size)
{
    const float*         node     = (const float*)d_in[0];
    const float*         edge     = (const float*)d_in[1];
    const unsigned char* mask     = (const unsigned char*)d_in[2];
    const float*         qkv_w    = (const float*)d_in[3];
    const float*         qkv_b    = (const float*)d_in[4];
    const float*         reduce_w = (const float*)d_in[5];
    const float*         reduce_b = (const float*)d_in[6];
    const float*         expand_w = (const float*)d_in[7];
    const float*         expand_b = (const float*)d_in[8];
    const float*         fc_w     = (const float*)d_in[9];
    const float*         fc_b     = (const float*)d_in[10];
    const float*         proj_w   = (const float*)d_in[11];
    const float*         proj_b   = (const float*)d_in[12];

    float* out_node = (float*)d_out;
    float* out_edge = (float*)d_out + NODE_OUT_ELEMS;

    float *p_qkv, *p_S, *p_W, *p_tmp;
    cudaGetSymbolAddress((void**)&p_qkv, g_qkv);
    cudaGetSymbolAddress((void**)&p_S,   g_S);
    cudaGetSymbolAddress((void**)&p_W,   g_W);
    cudaGetSymbolAddress((void**)&p_tmp, g_tmp);

    // 1. QKV projection: [4096,512] @ [1536,512]^T
    k_gemm<<<dim3(12, 32), 256>>>(node, qkv_w, qkv_b, p_qkv, BB*NN, 3*CC, CC);

    // 2. attention scores per (b,h)
    k_scores<<<dim3(8, 8, BB*HH), 256>>>(p_qkv, p_S);

    // 3. fused bias + softmax + edge expand + edge reduction
    k_fused<<<dim3(NN, BB), 512>>>(edge, mask, reduce_w, reduce_b,
                                   expand_w, expand_b, p_S, out_edge, p_W);

    // 4. node update a @ v
    k_av<<<dim3(4, BB*HH), 128>>>(p_S, p_qkv, p_tmp);

    // 5. + w @ fc^T + fc_b
    k_fc<<<BB*NN, 256>>>(p_W, fc_w, fc_b, p_tmp);

    // 6. final projection -> node output
    k_gemm<<<dim3(4, 32), 256>>>(p_tmp, proj_w, proj_b, out_node, BB*NN, CC, CC);
}

// round 2
// speedup vs baseline: 1.8179x; 1.8179x over previous
#include <cuda_runtime.h>
#include <math_constants.h>

// ---------------- problem dims ----------------
#define BB 8
#define NN 512
#define CC 512
#define EE 64
#define HH 16
#define SCALE 0.17677669529663687f   // 1/sqrt(32)
#define NODE_OUT_ELEMS (BB*NN*CC)

// ---------------- scratch ----------------
__device__ float g_qkv[(size_t)BB*NN*3*CC];   // [b*n][1536] (q|k|v)
__device__ float g_S[(size_t)BB*HH*NN*NN];    // scores -> softmax a
__device__ float g_W[(size_t)BB*NN*EE];       // [b,n,e]
__device__ float g_tmp[(size_t)BB*NN*CC];     // node accumulator

// ---------------- tf32 mma helpers ----------------
__device__ __forceinline__ unsigned f2tf(float f) {
    unsigned u; asm("cvt.rna.tf32.f32 %0, %1;" : "=r"(u) : "f"(f)); return u;
}
__device__ __forceinline__ void mma8(float& c0, float& c1, float& c2, float& c3,
                                     unsigned a0, unsigned a1, unsigned a2, unsigned a3,
                                     unsigned b0, unsigned b1) {
    asm("mma.sync.aligned.m16n8k8.row.col.f32.tf32.tf32.f32 "
        "{%0,%1,%2,%3}, {%4,%5,%6,%7}, {%8,%9}, {%0,%1,%2,%3};"
        : "+f"(c0), "+f"(c1), "+f"(c2), "+f"(c3)
        : "r"(a0), "r"(a1), "r"(a2), "r"(a3), "r"(b0), "r"(b1));
}

// =====================================================================
// Generic batched tf32 GEMM: C = scale * (A[M,K] @ Bw[N,K]^T) + bias
// Block tile 128x128, 256 threads (8 warps: 4m x 2n), warp tile 32x64.
// Batch via z: zb=z>>4, zh=z&15 with separate hi/lo pointer strides.
// M,N multiples of 128 (grid-exact); K multiple of 32.
// =====================================================================
__global__ __launch_bounds__(256) void k_gemm_mma(
    const float* __restrict__ A, const float* __restrict__ Bw,
    const float* __restrict__ bias, float* __restrict__ Cout,
    int K, int lda, int ldb, int ldc,
    size_t sAb, size_t sAh, size_t sBb, size_t sBh, size_t sCb, size_t sCh,
    float scale)
{
    __shared__ unsigned As[128][36];
    __shared__ unsigned Bs[128][36];

    const int z = blockIdx.z, zb = z >> 4, zh = z & 15;
    A    += (size_t)zb * sAb + (size_t)zh * sAh;
    Bw   += (size_t)zb * sBb + (size_t)zh * sBh;
    Cout += (size_t)zb * sCb + (size_t)zh * sCh;

    const int bm = blockIdx.y * 128, bn = blockIdx.x * 128;
    const int tid = threadIdx.x, lane = tid & 31, w = tid >> 5;
    const int wm = w >> 1, wn = w & 1, g = lane >> 2, tg = lane & 3;

    float acc[2][8][4];
#pragma unroll
    for (int i = 0; i < 2; i++)
#pragma unroll
        for (int j = 0; j < 8; j++)
#pragma unroll
            for (int q = 0; q < 4; q++) acc[i][j][q] = 0.f;

    for (int kc = 0; kc < K; kc += 32) {
#pragma unroll
        for (int t = tid; t < 1024; t += 256) {
            int row = t >> 3, kf = (t & 7) * 4;
            float4 v = *(const float4*)&A[(size_t)(bm + row) * lda + kc + kf];
            *(uint4*)&As[row][kf] = make_uint4(f2tf(v.x), f2tf(v.y), f2tf(v.z), f2tf(v.w));
        }
#pragma unroll
        for (int t = tid; t < 1024; t += 256) {
            int row = t >> 3, kf = (t & 7) * 4;
            float4 v = *(const float4*)&Bw[(size_t)(bn + row) * ldb + kc + kf];
            *(uint4*)&Bs[row][kf] = make_uint4(f2tf(v.x), f2tf(v.y), f2tf(v.z), f2tf(v.w));
        }
        __syncthreads();

#pragma unroll
        for (int s = 0; s < 4; s++) {
            unsigned a[2][4];
#pragma unroll
            for (int i = 0; i < 2; i++) {
                int r = wm * 32 + i * 16 + g;
                a[i][0] = As[r][s*8 + tg];     a[i][1] = As[r+8][s*8 + tg];
                a[i][2] = As[r][s*8 + 4 + tg]; a[i][3] = As[r+8][s*8 + 4 + tg];
            }
#pragma unroll
            for (int j = 0; j < 8; j++) {
                int c = wn * 64 + j * 8 + g;
                unsigned b0 = Bs[c][s*8 + tg], b1 = Bs[c][s*8 + 4 + tg];
                mma8(acc[0][j][0], acc[0][j][1], acc[0][j][2], acc[0][j][3],
                     a[0][0], a[0][1], a[0][2], a[0][3], b0, b1);
                mma8(acc[1][j][0], acc[1][j][1], acc[1][j][2], acc[1][j][3],
                     a[1][0], a[1][1], a[1][2], a[1][3], b0, b1);
            }
        }
        __syncthreads();
    }

#pragma unroll
    for (int i = 0; i < 2; i++)
#pragma unroll
        for (int j = 0; j < 8; j++) {
            int r = bm + wm * 32 + i * 16 + g;
            int c = bn + wn * 64 + j * 8 + 2 * tg;
            float b0v = 0.f, b1v = 0.f;
            if (bias) { float2 bb = *(const float2*)&bias[c]; b0v = bb.x; b1v = bb.y; }
            float2 o0 = { acc[i][j][0] * scale + b0v, acc[i][j][1] * scale + b1v };
            float2 o1 = { acc[i][j][2] * scale + b0v, acc[i][j][3] * scale + b1v };
            *(float2*)&Cout[(size_t)r * ldc + c] = o0;
            *(float2*)&Cout[(size_t)(r + 8) * ldc + c] = o1;
        }
}

// =====================================================================
// a @ v with tf32 mma: tmp[b,n,h*32+d] = sum_m a[bh,n,m] * v[b,m,h,d]
// Block: 256n x 32d per (b,h); 256 threads = 8 warps, warp tile 32n x 32d.
// grid (2, 128)
// =====================================================================
__global__ __launch_bounds__(256) void k_av_mma(
    const float* __restrict__ S, const float* __restrict__ qkv,
    float* __restrict__ tmp)
{
    __shared__ unsigned As[256][36];
    __shared__ unsigned Vs[32][36];

    const int z = blockIdx.y, b = z >> 4, h = z & 15;
    const float* Sa = S + (size_t)z * NN * NN;
    const float* Vb = qkv + (size_t)b * NN * 1536 + 1024 + h * 32;
    const int n0 = blockIdx.x * 256;
    const int tid = threadIdx.x, lane = tid & 31, w = tid >> 5;
    const int g = lane >> 2, tg = lane & 3;

    float acc[2][4][4];
#pragma unroll
    for (int i = 0; i < 2; i++)
#pragma unroll
        for (int j = 0; j < 4; j++)
#pragma unroll
            for (int q = 0; q < 4; q++) acc[i][j][q] = 0.f;

    for (int kc = 0; kc < NN; kc += 32) {
#pragma unroll
        for (int t = tid; t < 2048; t += 256) {
            int row = t >> 3, kf = (t & 7) * 4;
            float4 v = *(const float4*)&Sa[(size_t)(n0 + row) * NN + kc + kf];
            *(uint4*)&As[row][kf] = make_uint4(f2tf(v.x), f2tf(v.y), f2tf(v.z), f2tf(v.w));
        }
        if (tid < 256) {
            int row = tid >> 3, kf = (tid & 7) * 4;
            float4 v = *(const float4*)&Vb[(size_t)(kc + row) * 1536 + kf];
            *(uint4*)&Vs[row][kf] = make_uint4(f2tf(v.x), f2tf(v.y), f2tf(v.z), f2tf(v.w));
        }
        __syncthreads();

#pragma unroll
        for (int s = 0; s < 4; s++) {
            unsigned a[2][4];
#pragma unroll
            for (int i = 0; i < 2; i++) {
                int r = w * 32 + i * 16 + g;
                a[i][0] = As[r][s*8 + tg];     a[i][1] = As[r+8][s*8 + tg];
                a[i][2] = As[r][s*8 + 4 + tg]; a[i][3] = As[r+8][s*8 + 4 + tg];
            }
#pragma unroll
            for (int j = 0; j < 4; j++) {
                unsigned b0 = Vs[s*8 + tg][j*8 + g], b1 = Vs[s*8 + 4 + tg][j*8 + g];
                mma8(acc[0][j][0], acc[0][j][1], acc[0][j][2], acc[0][j][3],
                     a[0][0], a[0][1], a[0][2], a[0][3], b0, b1);
                mma8(acc[1][j][0], acc[1][j][1], acc[1][j][2], acc[1][j][3],
                     a[1][0], a[1][1], a[1][2], a[1][3], b0, b1);
            }
        }
        __syncthreads();
    }

#pragma unroll
    for (int i = 0; i < 2; i++)
#pragma unroll
        for (int j = 0; j < 4; j++) {
            int nn = n0 + w * 32 + i * 16 + g;
            int col = h * 32 + j * 8 + 2 * tg;
            float2 o0 = { acc[i][j][0], acc[i][j][1] };
            float2 o1 = { acc[i][j][2], acc[i][j][3] };
            *(float2*)&tmp[((size_t)b * NN + nn) * CC + col] = o0;
            *(float2*)&tmp[((size_t)b * NN + nn + 8) * CC + col] = o1;
        }
}

// =====================================================================
// Fused per-(b,n): edge-bias mma + attn softmax + residual + edge-expand
// mma + edge softmax-weighted reduction. 512 threads = 16 warps.
// Dynamic smem layout (bytes):
//   T   [512][17] f32                 @ 0        (34816)
//   union { Asu [64][132] tf32 ; Es [64][516] f32 } @ 34816  (132096)
//   rwT [16][68] tf32                 @ 166912   (4352)
//   ewT [16][68] tf32                 @ 171264   (4352)
//   eb  [64] f32                      @ 175616
//   rb  [16] f32                      @ 175872
//   mk  [512] u8                      @ 175936
// total 176448
// =====================================================================
#define FUSED_SMEM 176448

__global__ __launch_bounds__(512) void k_fused_mma(
    const float* __restrict__ edge, const unsigned char* __restrict__ mask,
    const float* __restrict__ reduce_w, const float* __restrict__ reduce_b,
    const float* __restrict__ expand_w, const float* __restrict__ expand_b,
    float* __restrict__ S, float* __restrict__ edge_out, float* __restrict__ Wg)
{
    extern __shared__ char sm[];
    float*    T   = (float*)sm;                         // [512][17]
    float*    Es  = (float*)(sm + 34816);               // [64][516]
    unsigned* Asu = (unsigned*)(sm + 34816);            // [64][132]
    unsigned* rwT = (unsigned*)(sm + 166912);           // [16][68] (h-major)
    unsigned* ewT = (unsigned*)(sm + 171264);           // [16][68] (h-major)
    float*    eb  = (float*)(sm + 175616);
    float*    rb  = (float*)(sm + 175872);
    unsigned char* mk = (unsigned char*)(sm + 175936);

    const int b = blockIdx.y, n = blockIdx.x;
    const int tid = threadIdx.x, lane = tid & 31, w = tid >> 5;
    const int g = lane >> 2, tg = lane & 3;

    // ---- setup ----
    for (int t = tid; t < 1024; t += 512) {
        int h = t >> 6, e = t & 63;
        rwT[h * 68 + e] = f2tf(reduce_w[t]);            // reduce_w is [H][E]
        int e2 = t >> 4, h2 = t & 15;
        ewT[h2 * 68 + e2] = f2tf(expand_w[t]);          // expand_w is [E][H]
    }
    if (tid < 64) eb[tid] = expand_b[tid];
    if (tid < 16) rb[tid] = reduce_b[tid];
    mk[tid] = mask[b * NN + tid];
    __syncthreads();

    const size_t ebase = ((size_t)b * EE) * NN * NN + (size_t)n * NN;
    const size_t sbase = ((size_t)b * HH) * NN * NN + (size_t)n * NN;

    // ---- phase 1: T[m][h] = S + rb[h] + sum_e edge[e][m]*rw[h][e] ----
    for (int c = 0; c < 4; c++) {
        const int m0 = c * 128;
#pragma unroll
        for (int t = tid; t < 2048; t += 512) {
            int e = t >> 5, mf = (t & 31) * 4;
            float4 v = *(const float4*)&edge[ebase + (size_t)e * NN * NN + m0 + mf];
            *(uint4*)&Asu[e * 132 + mf] = make_uint4(f2tf(v.x), f2tf(v.y), f2tf(v.z), f2tf(v.w));
        }
        __syncthreads();

        // warp w owns m-columns [m0+8w, m0+8w+8), all 16 h rows
        const int mcol = m0 + w * 8 + 2 * tg;
        float2 s0 = *(const float2*)&S[sbase + (size_t)g * NN * NN + mcol];
        float2 s1 = *(const float2*)&S[sbase + (size_t)(g + 8) * NN * NN + mcol];
        float c0 = s0.x, c1 = s0.y, c2 = s1.x, c3 = s1.y;
#pragma unroll
        for (int s = 0; s < 8; s++) {
            unsigned a0 = rwT[g * 68 + s*8 + tg];
            unsigned a1 = rwT[(g + 8) * 68 + s*8 + tg];
            unsigned a2 = rwT[g * 68 + s*8 + 4 + tg];
            unsigned a3 = rwT[(g + 8) * 68 + s*8 + 4 + tg];
            unsigned b0 = Asu[(s*8 + tg) * 132 + w * 8 + g];
            unsigned b1 = Asu[(s*8 + 4 + tg) * 132 + w * 8 + g];
            mma8(c0, c1, c2, c3, a0, a1, a2, a3, b0, b1);
        }
        c0 += rb[g]; c1 += rb[g]; c2 += rb[g + 8]; c3 += rb[g + 8];
        T[mcol * 17 + g]       = c0;
        T[(mcol + 1) * 17 + g] = c1;
        T[mcol * 17 + g + 8]       = c2;
        T[(mcol + 1) * 17 + g + 8] = c3;
        __syncthreads();
    }

    // ---- phase 2: per-head softmax (warp h) ----
    {
        const int h = w;
        float vals[16];
        float mx = -CUDART_INF_F;
#pragma unroll
        for (int i = 0; i < 16; i++) {
            int m = lane + 32 * i;
            vals[i] = T[m * 17 + h];
            if (!mk[m]) mx = fmaxf(mx, vals[i]);
        }
#pragma unroll
        for (int o = 16; o > 0; o >>= 1)
            mx = fmaxf(mx, __shfl_xor_sync(0xffffffffu, mx, o));

        float p[16], sum = 0.f;
#pragma unroll
        for (int i = 0; i < 16; i++) {
            int m = lane + 32 * i;
            p[i] = mk[m] ? 0.f : __expf(vals[i] - mx);
            sum += p[i];
        }
#pragma unroll
        for (int o = 16; o > 0; o >>= 1)
            sum += __shfl_xor_sync(0xffffffffu, sum, o);
        float inv = 1.f / sum;

#pragma unroll
        for (int i = 0; i < 16; i++) {
            int m = lane + 32 * i;
            float a = p[i] * inv;
            S[sbase + (size_t)h * NN * NN + m] = a;   // for a@v
            T[m * 17 + h] = a + vals[i];              // residual for edge update
        }
    }
    __syncthreads();

    // ---- phase 3: Es[e][m] = eb[e] + sum_h T[m][h]*ew[h][e] (mma) ----
    {
        float acc[2][8][4];
#pragma unroll
        for (int i = 0; i < 2; i++)
#pragma unroll
            for (int j = 0; j < 8; j++)
#pragma unroll
                for (int q = 0; q < 4; q++) acc[i][j][q] = 0.f;

#pragma unroll
        for (int s = 0; s < 2; s++) {
            unsigned a[2][4];
#pragma unroll
            for (int i = 0; i < 2; i++) {
                int m = w * 32 + i * 16 + g;
                a[i][0] = f2tf(T[m * 17 + s*8 + tg]);
                a[i][1] = f2tf(T[(m + 8) * 17 + s*8 + tg]);
                a[i][2] = f2tf(T[m * 17 + s*8 + 4 + tg]);
                a[i][3] = f2tf(T[(m + 8) * 17 + s*8 + 4 + tg]);
            }
#pragma unroll
            for (int j = 0; j < 8; j++) {
                unsigned b0 = ewT[(s*8 + tg) * 68 + j * 8 + g];
                unsigned b1 = ewT[(s*8 + 4 + tg) * 68 + j * 8 + g];
                mma8(acc[0][j][0], acc[0][j][1], acc[0][j][2], acc[0][j][3],
                     a[0][0], a[0][1], a[0][2], a[0][3], b0, b1);
                mma8(acc[1][j][0], acc[1][j][1], acc[1][j][2], acc[1][j][3],
                     a[1][0], a[1][1], a[1][2], a[1][3], b0, b1);
            }
        }
#pragma unroll
        for (int i = 0; i < 2; i++)
#pragma unroll
            for (int j = 0; j < 8; j++) {
                int m = w * 32 + i * 16 + g;
                int e = j * 8 + 2 * tg;
                float e0 = eb[e], e1 = eb[e + 1];
                Es[e * 516 + m]           = acc[i][j][0] + e0;
                Es[(e + 1) * 516 + m]     = acc[i][j][1] + e1;
                Es[e * 516 + m + 8]       = acc[i][j][2] + e0;
                Es[(e + 1) * 516 + m + 8] = acc[i][j][3] + e1;
            }
    }
    __syncthreads();

    // ---- phase 4: edge_out write + edge softmax-weighted reduction ----
    {
#pragma unroll
        for (int q = 0; q < 4; q++) {
            int e = w * 4 + q;
            float4 v[4];
            float mx = -CUDART_INF_F;
#pragma unroll
            for (int j = 0; j < 4; j++) {
                int m = 4 * lane + 128 * j;
                v[j] = *(float4*)&Es[e * 516 + m];
                *(float4*)&edge_out[ebase + (size_t)e * NN * NN + m] = v[j];
                const float* vv = (const float*)&v[j];
#pragma unroll
                for (int cmp = 0; cmp < 4; cmp++)
                    if (!mk[m + cmp]) mx = fmaxf(mx, vv[cmp]);
            }
#pragma unroll
            for (int o = 16; o > 0; o >>= 1)
                mx = fmaxf(mx, __shfl_xor_sync(0xffffffffu, mx, o));

            float sp = 0.f, spv = 0.f;
#pragma unroll
            for (int j = 0; j < 4; j++) {
                int m = 4 * lane + 128 * j;
                const float* vv = (const float*)&v[j];
#pragma unroll
                for (int cmp = 0; cmp < 4; cmp++) {
                    float pp = mk[m + cmp] ? 0.f : __expf(vv[cmp] - mx);
                    sp += pp;
                    spv += pp * vv[cmp];
                }
            }
#pragma unroll
            for (int o = 16; o > 0; o >>= 1) {
                sp  += __shfl_xor_sync(0xffffffffu, sp, o);
                spv += __shfl_xor_sync(0xffffffffu, spv, o);
            }
            if (lane == 0)
                Wg[((size_t)b * NN + n) * EE + e] = spv / sp;
        }
    }
}

// =====================================================================
// x += w @ fc_w^T + fc_b  (K=64)
// =====================================================================
__global__ __launch_bounds__(256) void k_fc(
    const float* __restrict__ Wg, const float* __restrict__ fc_w,
    const float* __restrict__ fc_b, float* __restrict__ x)
{
    __shared__ float ws[64];
    const int bn = blockIdx.x;
    const int tid = threadIdx.x;
    if (tid < 64) ws[tid] = Wg[(size_t)bn * EE + tid];
    __syncthreads();

    for (int c = tid; c < CC; c += 256) {
        float s = fc_b[c];
        const float4* f4 = (const float4*)&fc_w[(size_t)c * EE];
#pragma unroll
        for (int e4 = 0; e4 < 16; e4++) {
            float4 f = f4[e4];
            s += ws[e4*4+0]*f.x + ws[e4*4+1]*f.y + ws[e4*4+2]*f.z + ws[e4*4+3]*f.w;
        }
        x[(size_t)bn * CC + c] += s;
    }
}

// =====================================================================
extern "C" void kernel_launch(void* const* d_in, const int* in_sizes, int n_in,
                              void* d_out, int out_size)
{
    const float*         node     = (const float*)d_in[0];
    const float*         edge     = (const float*)d_in[1];
    const unsigned char* mask     = (const unsigned char*)d_in[2];
    const float*         qkv_w    = (const float*)d_in[3];
    const float*         qkv_b    = (const float*)d_in[4];
    const float*         reduce_w = (const float*)d_in[5];
    const float*         reduce_b = (const float*)d_in[6];
    const float*         expand_w = (const float*)d_in[7];
    const float*         expand_b = (const float*)d_in[8];
    const float*         fc_w     = (const float*)d_in[9];
    const float*         fc_b     = (const float*)d_in[10];
    const float*         proj_w   = (const float*)d_in[11];
    const float*         proj_b   = (const float*)d_in[12];

    float* out_node = (float*)d_out;
    float* out_edge = (float*)d_out + NODE_OUT_ELEMS;

    float *p_qkv, *p_S, *p_W, *p_tmp;
    cudaGetSymbolAddress((void**)&p_qkv, g_qkv);
    cudaGetSymbolAddress((void**)&p_S,   g_S);
    cudaGetSymbolAddress((void**)&p_W,   g_W);
    cudaGetSymbolAddress((void**)&p_tmp, g_tmp);

    cudaFuncSetAttribute(k_fused_mma, cudaFuncAttributeMaxDynamicSharedMemorySize, FUSED_SMEM);

    // 1. QKV projection: [4096,512] @ [1536,512]^T + b
    k_gemm_mma<<<dim3(12, 32, 1), 256>>>(node, qkv_w, qkv_b, p_qkv,
        512, 512, 512, 1536, 0, 0, 0, 0, 0, 0, 1.f);

    // 2. scores: per (b,h) Q[512,32] @ K[512,32]^T * SCALE
    k_gemm_mma<<<dim3(4, 4, 128), 256>>>(p_qkv, p_qkv + 512, nullptr, p_S,
        32, 1536, 1536, 512,
        (size_t)NN*1536, 32, (size_t)NN*1536, 32,
        (size_t)HH*NN*NN, (size_t)NN*NN, SCALE);

    // 3. fused bias + softmax + edge expand + edge reduction
    k_fused_mma<<<dim3(NN, BB), 512, FUSED_SMEM>>>(edge, mask, reduce_w, reduce_b,
        expand_w, expand_b, p_S, out_edge, p_W);

    // 4. node update a @ v
    k_av_mma<<<dim3(2, 128), 256>>>(p_S, p_qkv, p_tmp);

    // 5. + w @ fc^T + fc_b
    k_fc<<<BB*NN, 256>>>(p_W, fc_w, fc_b, p_tmp);

    // 6. final projection
    k_gemm_mma<<<dim3(4, 32, 1), 256>>>(p_tmp, proj_w, proj_b, out_node,
        512, 512, 512, 512, 0, 0, 0, 0, 0, 0, 1.f);
}

// round 3
// speedup vs baseline: 3.0230x; 1.6629x over previous
#include <cuda_runtime.h>
#include <math_constants.h>

// ---------------- problem dims ----------------
#define BB 8
#define NN 512
#define CC 512
#define EE 64
#define HH 16
#define SCALE 0.17677669529663687f   // 1/sqrt(32)
#define NODE_OUT_ELEMS (BB*NN*CC)
#define NNNN ((size_t)NN*NN)

// ---------------- scratch ----------------
__device__ float g_qkv[(size_t)BB*NN*3*CC];   // [b*n][1536] (q|k|v)
__device__ float g_S[(size_t)BB*HH*NN*NN];    // scores -> softmax a
__device__ float g_W[(size_t)BB*NN*EE];       // [b,n,e]
__device__ float g_tmp[(size_t)BB*NN*CC];     // node accumulator

// ---------------- tf32 mma helpers ----------------
__device__ __forceinline__ unsigned f2tf(float f) {
    unsigned u; asm("cvt.rna.tf32.f32 %0, %1;" : "=r"(u) : "f"(f)); return u;
}
__device__ __forceinline__ void mma8(float& c0, float& c1, float& c2, float& c3,
                                     unsigned a0, unsigned a1, unsigned a2, unsigned a3,
                                     unsigned b0, unsigned b1) {
    asm("mma.sync.aligned.m16n8k8.row.col.f32.tf32.tf32.f32 "
        "{%0,%1,%2,%3}, {%4,%5,%6,%7}, {%8,%9}, {%0,%1,%2,%3};"
        : "+f"(c0), "+f"(c1), "+f"(c2), "+f"(c3)
        : "r"(a0), "r"(a1), "r"(a2), "r"(a3), "r"(b0), "r"(b1));
}
__device__ __forceinline__ void cpa16(void* dst_smem, const void* src) {
    unsigned d = (unsigned)__cvta_generic_to_shared(dst_smem);
    asm volatile("cp.async.ca.shared.global [%0], [%1], 16;" :: "r"(d), "l"(src));
}

// =====================================================================
// Generic batched tf32 GEMM: C = scale * (A[M,K] @ Bw[N,K]^T) + bias
// Block tile 128x128, 256 threads (8 warps: 4m x 2n), warp tile 32x64.
// =====================================================================
__global__ __launch_bounds__(256) void k_gemm_mma(
    const float* __restrict__ A, const float* __restrict__ Bw,
    const float* __restrict__ bias, float* __restrict__ Cout,
    int K, int lda, int ldb, int ldc,
    size_t sAb, size_t sAh, size_t sBb, size_t sBh, size_t sCb, size_t sCh,
    float scale)
{
    __shared__ unsigned As[128][36];
    __shared__ unsigned Bs[128][36];

    const int z = blockIdx.z, zb = z >> 4, zh = z & 15;
    A    += (size_t)zb * sAb + (size_t)zh * sAh;
    Bw   += (size_t)zb * sBb + (size_t)zh * sBh;
    Cout += (size_t)zb * sCb + (size_t)zh * sCh;

    const int bm = blockIdx.y * 128, bn = blockIdx.x * 128;
    const int tid = threadIdx.x, lane = tid & 31, w = tid >> 5;
    const int wm = w >> 1, wn = w & 1, g = lane >> 2, tg = lane & 3;

    float acc[2][8][4];
#pragma unroll
    for (int i = 0; i < 2; i++)
#pragma unroll
        for (int j = 0; j < 8; j++)
#pragma unroll
            for (int q = 0; q < 4; q++) acc[i][j][q] = 0.f;

    for (int kc = 0; kc < K; kc += 32) {
#pragma unroll
        for (int t = tid; t < 1024; t += 256) {
            int row = t >> 3, kf = (t & 7) * 4;
            float4 v = *(const float4*)&A[(size_t)(bm + row) * lda + kc + kf];
            *(uint4*)&As[row][kf] = make_uint4(f2tf(v.x), f2tf(v.y), f2tf(v.z), f2tf(v.w));
        }
#pragma unroll
        for (int t = tid; t < 1024; t += 256) {
            int row = t >> 3, kf = (t & 7) * 4;
            float4 v = *(const float4*)&Bw[(size_t)(bn + row) * ldb + kc + kf];
            *(uint4*)&Bs[row][kf] = make_uint4(f2tf(v.x), f2tf(v.y), f2tf(v.z), f2tf(v.w));
        }
        __syncthreads();

#pragma unroll
        for (int s = 0; s < 4; s++) {
            unsigned a[2][4];
#pragma unroll
            for (int i = 0; i < 2; i++) {
                int r = wm * 32 + i * 16 + g;
                a[i][0] = As[r][s*8 + tg];     a[i][1] = As[r+8][s*8 + tg];
                a[i][2] = As[r][s*8 + 4 + tg]; a[i][3] = As[r+8][s*8 + 4 + tg];
            }
#pragma unroll
            for (int j = 0; j < 8; j++) {
                int c = wn * 64 + j * 8 + g;
                unsigned b0 = Bs[c][s*8 + tg], b1 = Bs[c][s*8 + 4 + tg];
                mma8(acc[0][j][0], acc[0][j][1], acc[0][j][2], acc[0][j][3],
                     a[0][0], a[0][1], a[0][2], a[0][3], b0, b1);
                mma8(acc[1][j][0], acc[1][j][1], acc[1][j][2], acc[1][j][3],
                     a[1][0], a[1][1], a[1][2], a[1][3], b0, b1);
            }
        }
        __syncthreads();
    }

#pragma unroll
    for (int i = 0; i < 2; i++)
#pragma unroll
        for (int j = 0; j < 8; j++) {
            int r = bm + wm * 32 + i * 16 + g;
            int c = bn + wn * 64 + j * 8 + 2 * tg;
            float b0v = 0.f, b1v = 0.f;
            if (bias) { float2 bb = *(const float2*)&bias[c]; b0v = bb.x; b1v = bb.y; }
            float2 o0 = { acc[i][j][0] * scale + b0v, acc[i][j][1] * scale + b1v };
            float2 o1 = { acc[i][j][2] * scale + b0v, acc[i][j][3] * scale + b1v };
            *(float2*)&Cout[(size_t)r * ldc + c] = o0;
            *(float2*)&Cout[(size_t)(r + 8) * ldc + c] = o1;
        }
}

// =====================================================================
// a @ v : tmp[b,n,h*32+d] = sum_m a[bh,n,m] * v[b,m,h,d]
// Block 128 threads (4 warps), tile 128n x 32d, grid (4, 128).
// =====================================================================
__global__ __launch_bounds__(128) void k_av_mma(
    const float* __restrict__ S, const float* __restrict__ qkv,
    float* __restrict__ tmp)
{
    __shared__ unsigned As[128][36];
    __shared__ unsigned Vs[32][36];

    const int z = blockIdx.y, b = z >> 4, h = z & 15;
    const float* Sa = S + (size_t)z * NNNN;
    const float* Vb = qkv + (size_t)b * NN * 1536 + 1024 + h * 32;
    const int n0 = blockIdx.x * 128;
    const int tid = threadIdx.x, lane = tid & 31, w = tid >> 5;
    const int g = lane >> 2, tg = lane & 3;

    float acc[2][4][4];
#pragma unroll
    for (int i = 0; i < 2; i++)
#pragma unroll
        for (int j = 0; j < 4; j++)
#pragma unroll
            for (int q = 0; q < 4; q++) acc[i][j][q] = 0.f;

    for (int kc = 0; kc < NN; kc += 32) {
#pragma unroll
        for (int t = tid; t < 1024; t += 128) {
            int row = t >> 3, kf = (t & 7) * 4;
            float4 v = *(const float4*)&Sa[(size_t)(n0 + row) * NN + kc + kf];
            *(uint4*)&As[row][kf] = make_uint4(f2tf(v.x), f2tf(v.y), f2tf(v.z), f2tf(v.w));
        }
#pragma unroll
        for (int t = tid; t < 256; t += 128) {
            int row = t >> 3, kf = (t & 7) * 4;
            float4 v = *(const float4*)&Vb[(size_t)(kc + row) * 1536 + kf];
            *(uint4*)&Vs[row][kf] = make_uint4(f2tf(v.x), f2tf(v.y), f2tf(v.z), f2tf(v.w));
        }
        __syncthreads();

#pragma unroll
        for (int s = 0; s < 4; s++) {
            unsigned a[2][4];
#pragma unroll
            for (int i = 0; i < 2; i++) {
                int r = w * 32 + i * 16 + g;
                a[i][0] = As[r][s*8 + tg];     a[i][1] = As[r+8][s*8 + tg];
                a[i][2] = As[r][s*8 + 4 + tg]; a[i][3] = As[r+8][s*8 + 4 + tg];
            }
#pragma unroll
            for (int j = 0; j < 4; j++) {
                unsigned b0 = Vs[s*8 + tg][j*8 + g], b1 = Vs[s*8 + 4 + tg][j*8 + g];
                mma8(acc[0][j][0], acc[0][j][1], acc[0][j][2], acc[0][j][3],
                     a[0][0], a[0][1], a[0][2], a[0][3], b0, b1);
                mma8(acc[1][j][0], acc[1][j][1], acc[1][j][2], acc[1][j][3],
                     a[1][0], a[1][1], a[1][2], a[1][3], b0, b1);
            }
        }
        __syncthreads();
    }

#pragma unroll
    for (int i = 0; i < 2; i++)
#pragma unroll
        for (int j = 0; j < 4; j++) {
            int nn = n0 + w * 32 + i * 16 + g;
            int col = h * 32 + j * 8 + 2 * tg;
            float2 o0 = { acc[i][j][0], acc[i][j][1] };
            float2 o1 = { acc[i][j][2], acc[i][j][3] };
            *(float2*)&tmp[((size_t)b * NN + nn) * CC + col] = o0;
            *(float2*)&tmp[((size_t)b * NN + nn + 8) * CC + col] = o1;
        }
}

// =====================================================================
// Fused per-(b,n). 512 threads, 16 warps, 2 CTAs/SM.
// smem layout (bytes):
//   T    [512][17] f32   @ 0       34816
//   buf0 [64][132] f32   @ 34816   33792   (also [16][516] in phase 4)
//   buf1 [64][132] f32   @ 68608   33792
//   rwT  [16][68]  tf32  @ 102400  4352
//   ewT  [16][68]  tf32  @ 106752  4352
//   eb   [64] f32        @ 111104  256
//   rb   [16] f32        @ 111360  64
//   mk   [512] u8        @ 111424  512
// total 111936  -> 2 CTAs/SM
// =====================================================================
#define FUSED_SMEM 111936

__global__ __launch_bounds__(512, 2) void k_fused_mma(
    const float* __restrict__ edge, const unsigned char* __restrict__ mask,
    const float* __restrict__ reduce_w, const float* __restrict__ reduce_b,
    const float* __restrict__ expand_w, const float* __restrict__ expand_b,
    float* __restrict__ S, float* __restrict__ edge_out, float* __restrict__ Wg)
{
    extern __shared__ char sm[];
    float*    T    = (float*)sm;
    float*    buf0 = (float*)(sm + 34816);
    float*    buf1 = (float*)(sm + 68608);
    unsigned* rwT  = (unsigned*)(sm + 102400);
    unsigned* ewT  = (unsigned*)(sm + 106752);
    float*    eb   = (float*)(sm + 111104);
    float*    rb   = (float*)(sm + 111360);
    unsigned char* mk = (unsigned char*)(sm + 111424);

    const int b = blockIdx.y, n = blockIdx.x;
    const int tid = threadIdx.x, lane = tid & 31, w = tid >> 5;
    const int g = lane >> 2, tg = lane & 3;

    const size_t ebase = ((size_t)b * EE) * NNNN + (size_t)n * NN;
    const size_t sbase = ((size_t)b * HH) * NNNN + (size_t)n * NN;

    // ---- setup ----
    for (int t = tid; t < 1024; t += 512) {
        int h = t >> 6, e = t & 63;
        rwT[h * 68 + e] = f2tf(reduce_w[t]);            // reduce_w [H][E]
        int e2 = t >> 4, h2 = t & 15;
        ewT[h2 * 68 + e2] = f2tf(expand_w[t]);          // expand_w [E][H]
    }
    if (tid < 64) eb[tid] = expand_b[tid];
    if (tid < 16) rb[tid] = reduce_b[tid];
    mk[tid] = mask[b * NN + tid];

    // prefetch chunks 0,1 of edge (raw f32, converted at use)
    float* bufs[2] = { buf0, buf1 };
    {
#pragma unroll
        for (int t = tid; t < 2048; t += 512) {
            int e = t >> 5, mf = (t & 31) * 4;
            cpa16(buf0 + e * 132 + mf, edge + ebase + (size_t)e * NNNN + 0 + mf);
        }
        asm volatile("cp.async.commit_group;");
#pragma unroll
        for (int t = tid; t < 2048; t += 512) {
            int e = t >> 5, mf = (t & 31) * 4;
            cpa16(buf1 + e * 132 + mf, edge + ebase + (size_t)e * NNNN + 128 + mf);
        }
        asm volatile("cp.async.commit_group;");
    }
    __syncthreads();   // setup visible

    // ---- phase 1: T[m][h] = S + rb[h] + sum_e edge[e][m]*rw[h][e] ----
#pragma unroll
    for (int c = 0; c < 4; c++) {
        if (c < 3) asm volatile("cp.async.wait_group 1;");
        else       asm volatile("cp.async.wait_group 0;");
        __syncthreads();

        const float* Bf = bufs[c & 1];
        const int m0 = c * 128;
        const int mcol = m0 + w * 8 + 2 * tg;

        float2 s0 = *(const float2*)&S[sbase + (size_t)g * NNNN + mcol];
        float2 s1 = *(const float2*)&S[sbase + (size_t)(g + 8) * NNNN + mcol];
        float c0 = s0.x, c1 = s0.y, c2 = s1.x, c3 = s1.y;
#pragma unroll
        for (int s = 0; s < 8; s++) {
            unsigned a0 = rwT[g * 68 + s*8 + tg];
            unsigned a1 = rwT[(g + 8) * 68 + s*8 + tg];
            unsigned a2 = rwT[g * 68 + s*8 + 4 + tg];
            unsigned a3 = rwT[(g + 8) * 68 + s*8 + 4 + tg];
            unsigned b0 = f2tf(Bf[(s*8 + tg) * 132 + w * 8 + g]);
            unsigned b1 = f2tf(Bf[(s*8 + 4 + tg) * 132 + w * 8 + g]);
            mma8(c0, c1, c2, c3, a0, a1, a2, a3, b0, b1);
        }
        c0 += rb[g]; c1 += rb[g]; c2 += rb[g + 8]; c3 += rb[g + 8];
        T[mcol * 17 + g]           = c0;
        T[(mcol + 1) * 17 + g]     = c1;
        T[mcol * 17 + g + 8]       = c2;
        T[(mcol + 1) * 17 + g + 8] = c3;
        __syncthreads();

        if (c + 2 < 4) {
            float* dst = bufs[c & 1];
            const int m0n = (c + 2) * 128;
#pragma unroll
            for (int t = tid; t < 2048; t += 512) {
                int e = t >> 5, mf = (t & 31) * 4;
                cpa16(dst + e * 132 + mf, edge + ebase + (size_t)e * NNNN + m0n + mf);
            }
            asm volatile("cp.async.commit_group;");
        }
    }

    // ---- phase 2: per-head softmax (warp h) ----
    {
        const int h = w;
        float vals[16];
        float mx = -CUDART_INF_F;
#pragma unroll
        for (int i = 0; i < 16; i++) {
            int m = lane + 32 * i;
            vals[i] = T[m * 17 + h];
            if (!mk[m]) mx = fmaxf(mx, vals[i]);
        }
#pragma unroll
        for (int o = 16; o > 0; o >>= 1)
            mx = fmaxf(mx, __shfl_xor_sync(0xffffffffu, mx, o));

        float p[16], sum = 0.f;
#pragma unroll
        for (int i = 0; i < 16; i++) {
            int m = lane + 32 * i;
            p[i] = mk[m] ? 0.f : __expf(vals[i] - mx);
            sum += p[i];
        }
#pragma unroll
        for (int o = 16; o > 0; o >>= 1)
            sum += __shfl_xor_sync(0xffffffffu, sum, o);
        float inv = 1.f / sum;

#pragma unroll
        for (int i = 0; i < 16; i++) {
            int m = lane + 32 * i;
            float a = p[i] * inv;
            S[sbase + (size_t)h * NNNN + m] = a;   // for a@v
            T[m * 17 + h] = a + vals[i];           // residual for edge update
        }
    }
    __syncthreads();

    // ---- phase 3+4: edge expand mma (16-e groups) + write + reduction ----
    {
        // A fragments from T (reused across groups)
        unsigned af[2][2][4];
#pragma unroll
        for (int s = 0; s < 2; s++)
#pragma unroll
            for (int i = 0; i < 2; i++) {
                int m = w * 32 + i * 16 + g;
                af[s][i][0] = f2tf(T[m * 17 + s*8 + tg]);
                af[s][i][1] = f2tf(T[(m + 8) * 17 + s*8 + tg]);
                af[s][i][2] = f2tf(T[m * 17 + s*8 + 4 + tg]);
                af[s][i][3] = f2tf(T[(m + 8) * 17 + s*8 + 4 + tg]);
            }

#pragma unroll
        for (int grp = 0; grp < 4; grp++) {
            float acc[2][2][4];
#pragma unroll
            for (int i = 0; i < 2; i++)
#pragma unroll
                for (int jj = 0; jj < 2; jj++)
#pragma unroll
                    for (int q = 0; q < 4; q++) acc[i][jj][q] = 0.f;

#pragma unroll
            for (int s = 0; s < 2; s++)
#pragma unroll
                for (int jj = 0; jj < 2; jj++) {
                    int j = grp * 2 + jj;
                    unsigned b0 = ewT[(s*8 + tg) * 68 + j * 8 + g];
                    unsigned b1 = ewT[(s*8 + 4 + tg) * 68 + j * 8 + g];
                    mma8(acc[0][jj][0], acc[0][jj][1], acc[0][jj][2], acc[0][jj][3],
                         af[s][0][0], af[s][0][1], af[s][0][2], af[s][0][3], b0, b1);
                    mma8(acc[1][jj][0], acc[1][jj][1], acc[1][jj][2], acc[1][jj][3],
                         af[s][1][0], af[s][1][1], af[s][1][2], af[s][1][3], b0, b1);
                }

            float* buf = bufs[grp & 1];
            __syncthreads();   // buffer free (prev consume done)
#pragma unroll
            for (int i = 0; i < 2; i++)
#pragma unroll
                for (int jj = 0; jj < 2; jj++) {
                    int m = w * 32 + i * 16 + g;
                    int el = jj * 8 + 2 * tg;
                    int e = grp * 16 + el;
                    buf[el * 516 + m]           = acc[i][jj][0] + eb[e];
                    buf[(el + 1) * 516 + m]     = acc[i][jj][1] + eb[e + 1];
                    buf[el * 516 + m + 8]       = acc[i][jj][2] + eb[e];
                    buf[(el + 1) * 516 + m + 8] = acc[i][jj][3] + eb[e + 1];
                }
            __syncthreads();

            // consume: warp w <-> local e row w
            int e = grp * 16 + w;
            float4 v[4];
            float mx = -CUDART_INF_F;
#pragma unroll
            for (int k = 0; k < 4; k++) {
                int m = 4 * lane + 128 * k;
                v[k] = *(float4*)&buf[w * 516 + m];
                *(float4*)&edge_out[ebase + (size_t)e * NNNN + m] = v[k];
                const float* vv = (const float*)&v[k];
#pragma unroll
                for (int cmp = 0; cmp < 4; cmp++)
                    if (!mk[m + cmp]) mx = fmaxf(mx, vv[cmp]);
            }
#pragma unroll
            for (int o = 16; o > 0; o >>= 1)
                mx = fmaxf(mx, __shfl_xor_sync(0xffffffffu, mx, o));

            float sp = 0.f, spv = 0.f;
#pragma unroll
            for (int k = 0; k < 4; k++) {
                int m = 4 * lane + 128 * k;
                const float* vv = (const float*)&v[k];
#pragma unroll
                for (int cmp = 0; cmp < 4; cmp++) {
                    float pp = mk[m + cmp] ? 0.f : __expf(vv[cmp] - mx);
                    sp += pp;
                    spv += pp * vv[cmp];
                }
            }
#pragma unroll
            for (int o = 16; o > 0; o >>= 1) {
                sp  += __shfl_xor_sync(0xffffffffu, sp, o);
                spv += __shfl_xor_sync(0xffffffffu, spv, o);
            }
            if (lane == 0)
                Wg[((size_t)b * NN + n) * EE + e] = spv / sp;
        }
    }
}

// =====================================================================
// x += w @ fc_w^T + fc_b  (K=64)
// =====================================================================
__global__ __launch_bounds__(256) void k_fc(
    const float* __restrict__ Wg, const float* __restrict__ fc_w,
    const float* __restrict__ fc_b, float* __restrict__ x)
{
    __shared__ float ws[64];
    const int bn = blockIdx.x;
    const int tid = threadIdx.x;
    if (tid < 64) ws[tid] = Wg[(size_t)bn * EE + tid];
    __syncthreads();

    for (int c = tid; c < CC; c += 256) {
        float s = fc_b[c];
        const float4* f4 = (const float4*)&fc_w[(size_t)c * EE];
#pragma unroll
        for (int e4 = 0; e4 < 16; e4++) {
            float4 f = f4[e4];
            s += ws[e4*4+0]*f.x + ws[e4*4+1]*f.y + ws[e4*4+2]*f.z + ws[e4*4+3]*f.w;
        }
        x[(size_t)bn * CC + c] += s;
    }
}

// =====================================================================
extern "C" void kernel_launch(void* const* d_in, const int* in_sizes, int n_in,
                              void* d_out, int out_size)
{
    const float*         node     = (const float*)d_in[0];
    const float*         edge     = (const float*)d_in[1];
    const unsigned char* mask     = (const unsigned char*)d_in[2];
    const float*         qkv_w    = (const float*)d_in[3];
    const float*         qkv_b    = (const float*)d_in[4];
    const float*         reduce_w = (const float*)d_in[5];
    const float*         reduce_b = (const float*)d_in[6];
    const float*         expand_w = (const float*)d_in[7];
    const float*         expand_b = (const float*)d_in[8];
    const float*         fc_w     = (const float*)d_in[9];
    const float*         fc_b     = (const float*)d_in[10];
    const float*         proj_w   = (const float*)d_in[11];
    const float*         proj_b   = (const float*)d_in[12];

    float* out_node = (float*)d_out;
    float* out_edge = (float*)d_out + NODE_OUT_ELEMS;

    float *p_qkv, *p_S, *p_W, *p_tmp;
    cudaGetSymbolAddress((void**)&p_qkv, g_qkv);
    cudaGetSymbolAddress((void**)&p_S,   g_S);
    cudaGetSymbolAddress((void**)&p_W,   g_W);
    cudaGetSymbolAddress((void**)&p_tmp, g_tmp);

    cudaFuncSetAttribute(k_fused_mma, cudaFuncAttributeMaxDynamicSharedMemorySize, FUSED_SMEM);

    // 1. QKV projection: [4096,512] @ [1536,512]^T + b
    k_gemm_mma<<<dim3(12, 32, 1), 256>>>(node, qkv_w, qkv_b, p_qkv,
        512, 512, 512, 1536, 0, 0, 0, 0, 0, 0, 1.f);

    // 2. scores: per (b,h) Q[512,32] @ K[512,32]^T * SCALE
    k_gemm_mma<<<dim3(4, 4, 128), 256>>>(p_qkv, p_qkv + 512, nullptr, p_S,
        32, 1536, 1536, 512,
        (size_t)NN*1536, 32, (size_t)NN*1536, 32,
        (size_t)HH*NN*NN, (size_t)NN*NN, SCALE);

    // 3. fused bias + softmax + edge expand + edge reduction
    k_fused_mma<<<dim3(NN, BB), 512, FUSED_SMEM>>>(edge, mask, reduce_w, reduce_b,
        expand_w, expand_b, p_S, out_edge, p_W);

    // 4. node update a @ v
    k_av_mma<<<dim3(4, 128), 128>>>(p_S, p_qkv, p_tmp);

    // 5. + w @ fc^T + fc_b
    k_fc<<<BB*NN, 256>>>(p_W, fc_w, fc_b, p_tmp);

    // 6. final projection
    k_gemm_mma<<<dim3(4, 32, 1), 256>>>(p_tmp, proj_w, proj_b, out_node,
        512, 512, 512, 512, 0, 0, 0, 0, 0, 0, 1.f);
}

// round 4
// speedup vs baseline: 3.4732x; 1.1489x over previous
#include <cuda_runtime.h>
#include <math_constants.h>

// ---------------- problem dims ----------------
#define BB 8
#define NN 512
#define CC 512
#define EE 64
#define HH 16
#define SCALE 0.17677669529663687f   // 1/sqrt(32)
#define NODE_OUT_ELEMS (BB*NN*CC)
#define NNNN ((size_t)NN*NN)

// ---------------- scratch ----------------
__device__ float g_qkv[(size_t)BB*NN*3*CC];   // [b*n][1536] (q|k|v)
__device__ float g_S[(size_t)BB*HH*NN*NN];    // scores -> softmax a
__device__ float g_W[(size_t)BB*NN*EE];       // [b,n,e]
__device__ float g_tmp[(size_t)BB*NN*CC];     // node accumulator

// ---------------- helpers ----------------
__device__ __forceinline__ unsigned f2tf(float f) {
    unsigned u; asm("cvt.rna.tf32.f32 %0, %1;" : "=r"(u) : "f"(f)); return u;
}
__device__ __forceinline__ void mma8(float& c0, float& c1, float& c2, float& c3,
                                     unsigned a0, unsigned a1, unsigned a2, unsigned a3,
                                     unsigned b0, unsigned b1) {
    asm("mma.sync.aligned.m16n8k8.row.col.f32.tf32.tf32.f32 "
        "{%0,%1,%2,%3}, {%4,%5,%6,%7}, {%8,%9}, {%0,%1,%2,%3};"
        : "+f"(c0), "+f"(c1), "+f"(c2), "+f"(c3)
        : "r"(a0), "r"(a1), "r"(a2), "r"(a3), "r"(b0), "r"(b1));
}
__device__ __forceinline__ void cpa16(void* dst_smem, const void* src) {
    unsigned d = (unsigned)__cvta_generic_to_shared(dst_smem);
    asm volatile("cp.async.cg.shared.global [%0], [%1], 16;" :: "r"(d), "l"(src));
}
#define CP_COMMIT() asm volatile("cp.async.commit_group;")
#define CP_WAIT(n)  asm volatile("cp.async.wait_group %0;" :: "n"(n))

// =====================================================================
// Generic batched tf32 GEMM: C = scale*(A[M,K] @ Bw[N,K]^T) + bias
// Block tile 128x128, 256 threads (8 warps: 4m x 2n), warp tile 32x64.
// 2-stage cp.async pipeline; raw f32 staged, tf32 convert at frag read.
// dyn smem: 2 stages * (A 128x36 + B 128x36) f32 = 73728 B
// =====================================================================
#define GEMM_SMEM 73728

__global__ __launch_bounds__(256) void k_gemm_mma(
    const float* __restrict__ A, const float* __restrict__ Bw,
    const float* __restrict__ bias, float* __restrict__ Cout,
    int K, int lda, int ldb, int ldc,
    size_t sAb, size_t sAh, size_t sBb, size_t sBh, size_t sCb, size_t sCh,
    float scale)
{
    extern __shared__ float gsm[];   // stage s: A at s*9216, B at s*9216+4608

    const int z = blockIdx.z, zb = z >> 4, zh = z & 15;
    A    += (size_t)zb * sAb + (size_t)zh * sAh;
    Bw   += (size_t)zb * sBb + (size_t)zh * sBh;
    Cout += (size_t)zb * sCb + (size_t)zh * sCh;

    const int bm = blockIdx.y * 128, bn = blockIdx.x * 128;
    const int tid = threadIdx.x, lane = tid & 31, w = tid >> 5;
    const int wm = w >> 1, wn = w & 1, g = lane >> 2, tg = lane & 3;
    const int nchunks = K >> 5;

    float acc[2][8][4];
#pragma unroll
    for (int i = 0; i < 2; i++)
#pragma unroll
        for (int j = 0; j < 8; j++)
#pragma unroll
            for (int q = 0; q < 4; q++) acc[i][j][q] = 0.f;

    // prefetch chunk 0
    {
        float* As = gsm, * Bs = gsm + 4608;
#pragma unroll
        for (int t = tid; t < 1024; t += 256) {
            int row = t >> 3, kf = (t & 7) * 4;
            cpa16(As + row * 36 + kf, A + (size_t)(bm + row) * lda + kf);
        }
#pragma unroll
        for (int t = tid; t < 1024; t += 256) {
            int row = t >> 3, kf = (t & 7) * 4;
            cpa16(Bs + row * 36 + kf, Bw + (size_t)(bn + row) * ldb + kf);
        }
        CP_COMMIT();
    }

    for (int c = 0; c < nchunks; c++) {
        if (c + 1 < nchunks) {
            float* As = gsm + ((c + 1) & 1) * 9216, * Bs = As + 4608;
            int kc = (c + 1) << 5;
#pragma unroll
            for (int t = tid; t < 1024; t += 256) {
                int row = t >> 3, kf = (t & 7) * 4;
                cpa16(As + row * 36 + kf, A + (size_t)(bm + row) * lda + kc + kf);
            }
#pragma unroll
            for (int t = tid; t < 1024; t += 256) {
                int row = t >> 3, kf = (t & 7) * 4;
                cpa16(Bs + row * 36 + kf, Bw + (size_t)(bn + row) * ldb + kc + kf);
            }
            CP_COMMIT();
            CP_WAIT(1);
        } else {
            CP_WAIT(0);
        }
        __syncthreads();

        const float* As = gsm + (c & 1) * 9216;
        const float* Bs = As + 4608;
#pragma unroll
        for (int s = 0; s < 4; s++) {
            unsigned a[2][4];
#pragma unroll
            for (int i = 0; i < 2; i++) {
                int r = wm * 32 + i * 16 + g;
                a[i][0] = f2tf(As[r * 36 + s*8 + tg]);
                a[i][1] = f2tf(As[(r+8) * 36 + s*8 + tg]);
                a[i][2] = f2tf(As[r * 36 + s*8 + 4 + tg]);
                a[i][3] = f2tf(As[(r+8) * 36 + s*8 + 4 + tg]);
            }
#pragma unroll
            for (int j = 0; j < 8; j++) {
                int cc = wn * 64 + j * 8 + g;
                unsigned b0 = f2tf(Bs[cc * 36 + s*8 + tg]);
                unsigned b1 = f2tf(Bs[cc * 36 + s*8 + 4 + tg]);
                mma8(acc[0][j][0], acc[0][j][1], acc[0][j][2], acc[0][j][3],
                     a[0][0], a[0][1], a[0][2], a[0][3], b0, b1);
                mma8(acc[1][j][0], acc[1][j][1], acc[1][j][2], acc[1][j][3],
                     a[1][0], a[1][1], a[1][2], a[1][3], b0, b1);
            }
        }
        __syncthreads();
    }

#pragma unroll
    for (int i = 0; i < 2; i++)
#pragma unroll
        for (int j = 0; j < 8; j++) {
            int r = bm + wm * 32 + i * 16 + g;
            int cc = bn + wn * 64 + j * 8 + 2 * tg;
            float b0v = 0.f, b1v = 0.f;
            if (bias) { float2 bb = *(const float2*)&bias[cc]; b0v = bb.x; b1v = bb.y; }
            float2 o0 = { acc[i][j][0] * scale + b0v, acc[i][j][1] * scale + b1v };
            float2 o1 = { acc[i][j][2] * scale + b0v, acc[i][j][3] * scale + b1v };
            *(float2*)&Cout[(size_t)r * ldc + cc] = o0;
            *(float2*)&Cout[(size_t)(r + 8) * ldc + cc] = o1;
        }
}

// =====================================================================
// a @ v : tmp[b,n,h*32+d] = sum_m a[bh,n,m] * v[b,m,h,d]
// 128 threads (4 warps), tile 128n x 32d, grid (4, 128).
// 2-stage cp.async pipeline. dyn smem: 2*(128*36+32*36)*4 = 46080 B
// =====================================================================
#define AV_SMEM 46080

__global__ __launch_bounds__(128) void k_av_mma(
    const float* __restrict__ S, const float* __restrict__ qkv,
    float* __restrict__ tmp)
{
    extern __shared__ float avs[];   // stage s: A at s*5760, V at s*5760+4608

    const int z = blockIdx.y, b = z >> 4, h = z & 15;
    const float* Sa = S + (size_t)z * NNNN;
    const float* Vb = qkv + (size_t)b * NN * 1536 + 1024 + h * 32;
    const int n0 = blockIdx.x * 128;
    const int tid = threadIdx.x, lane = tid & 31, w = tid >> 5;
    const int g = lane >> 2, tg = lane & 3;

    float acc[2][4][4];
#pragma unroll
    for (int i = 0; i < 2; i++)
#pragma unroll
        for (int j = 0; j < 4; j++)
#pragma unroll
            for (int q = 0; q < 4; q++) acc[i][j][q] = 0.f;

    // prefetch chunk 0
    {
        float* As = avs, * Vs = avs + 4608;
#pragma unroll
        for (int t = tid; t < 1024; t += 128) {
            int row = t >> 3, kf = (t & 7) * 4;
            cpa16(As + row * 36 + kf, Sa + (size_t)(n0 + row) * NN + kf);
        }
#pragma unroll
        for (int t = tid; t < 256; t += 128) {
            int row = t >> 3, kf = (t & 7) * 4;
            cpa16(Vs + row * 36 + kf, Vb + (size_t)row * 1536 + kf);
        }
        CP_COMMIT();
    }

    for (int c = 0; c < 16; c++) {
        if (c + 1 < 16) {
            float* As = avs + ((c + 1) & 1) * 5760, * Vs = As + 4608;
            int kc = (c + 1) << 5;
#pragma unroll
            for (int t = tid; t < 1024; t += 128) {
                int row = t >> 3, kf = (t & 7) * 4;
                cpa16(As + row * 36 + kf, Sa + (size_t)(n0 + row) * NN + kc + kf);
            }
#pragma unroll
            for (int t = tid; t < 256; t += 128) {
                int row = t >> 3, kf = (t & 7) * 4;
                cpa16(Vs + row * 36 + kf, Vb + (size_t)(kc + row) * 1536 + kf);
            }
            CP_COMMIT();
            CP_WAIT(1);
        } else {
            CP_WAIT(0);
        }
        __syncthreads();

        const float* As = avs + (c & 1) * 5760;
        const float* Vs = As + 4608;
#pragma unroll
        for (int s = 0; s < 4; s++) {
            unsigned a[2][4];
#pragma unroll
            for (int i = 0; i < 2; i++) {
                int r = w * 32 + i * 16 + g;
                a[i][0] = f2tf(As[r * 36 + s*8 + tg]);
                a[i][1] = f2tf(As[(r+8) * 36 + s*8 + tg]);
                a[i][2] = f2tf(As[r * 36 + s*8 + 4 + tg]);
                a[i][3] = f2tf(As[(r+8) * 36 + s*8 + 4 + tg]);
            }
#pragma unroll
            for (int j = 0; j < 4; j++) {
                unsigned b0 = f2tf(Vs[(s*8 + tg) * 36 + j*8 + g]);
                unsigned b1 = f2tf(Vs[(s*8 + 4 + tg) * 36 + j*8 + g]);
                mma8(acc[0][j][0], acc[0][j][1], acc[0][j][2], acc[0][j][3],
                     a[0][0], a[0][1], a[0][2], a[0][3], b0, b1);
                mma8(acc[1][j][0], acc[1][j][1], acc[1][j][2], acc[1][j][3],
                     a[1][0], a[1][1], a[1][2], a[1][3], b0, b1);
            }
        }
        __syncthreads();
    }

#pragma unroll
    for (int i = 0; i < 2; i++)
#pragma unroll
        for (int j = 0; j < 4; j++) {
            int nn = n0 + w * 32 + i * 16 + g;
            int col = h * 32 + j * 8 + 2 * tg;
            float2 o0 = { acc[i][j][0], acc[i][j][1] };
            float2 o1 = { acc[i][j][2], acc[i][j][3] };
            *(float2*)&tmp[((size_t)b * NN + nn) * CC + col] = o0;
            *(float2*)&tmp[((size_t)b * NN + nn + 8) * CC + col] = o1;
        }
}

// =====================================================================
// Fused per-(b,n). 512 threads, 16 warps, 2 CTAs/SM. smem 111936 B.
// =====================================================================
#define FUSED_SMEM 111936

__global__ __launch_bounds__(512, 2) void k_fused_mma(
    const float* __restrict__ edge, const unsigned char* __restrict__ mask,
    const float* __restrict__ reduce_w, const float* __restrict__ reduce_b,
    const float* __restrict__ expand_w, const float* __restrict__ expand_b,
    float* __restrict__ S, float* __restrict__ edge_out, float* __restrict__ Wg)
{
    extern __shared__ char sm[];
    float*    T    = (float*)sm;                 // [512][17]
    float*    buf0 = (float*)(sm + 34816);       // [64][132] / [16][516]
    float*    buf1 = (float*)(sm + 68608);
    unsigned* rwT  = (unsigned*)(sm + 102400);   // [16][68]
    unsigned* ewT  = (unsigned*)(sm + 106752);   // [16][68]
    float*    eb   = (float*)(sm + 111104);
    float*    rb   = (float*)(sm + 111360);
    unsigned char* mk = (unsigned char*)(sm + 111424);

    const int b = blockIdx.y, n = blockIdx.x;
    const int tid = threadIdx.x, lane = tid & 31, w = tid >> 5;
    const int g = lane >> 2, tg = lane & 3;

    const size_t ebase = ((size_t)b * EE) * NNNN + (size_t)n * NN;
    const size_t sbase = ((size_t)b * HH) * NNNN + (size_t)n * NN;

    // ---- setup ----
    for (int t = tid; t < 1024; t += 512) {
        int h = t >> 6, e = t & 63;
        rwT[h * 68 + e] = f2tf(reduce_w[t]);            // reduce_w [H][E]
        int e2 = t >> 4, h2 = t & 15;
        ewT[h2 * 68 + e2] = f2tf(expand_w[t]);          // expand_w [E][H]
    }
    if (tid < 64) eb[tid] = expand_b[tid];
    if (tid < 16) rb[tid] = reduce_b[tid];
    mk[tid] = mask[b * NN + tid];

    float* bufs[2] = { buf0, buf1 };
    {
#pragma unroll
        for (int t = tid; t < 2048; t += 512) {
            int e = t >> 5, mf = (t & 31) * 4;
            cpa16(buf0 + e * 132 + mf, edge + ebase + (size_t)e * NNNN + 0 + mf);
        }
        CP_COMMIT();
#pragma unroll
        for (int t = tid; t < 2048; t += 512) {
            int e = t >> 5, mf = (t & 31) * 4;
            cpa16(buf1 + e * 132 + mf, edge + ebase + (size_t)e * NNNN + 128 + mf);
        }
        CP_COMMIT();
    }
    __syncthreads();

    // ---- phase 1: T[m][h] = S + rb[h] + sum_e edge[e][m]*rw[h][e] ----
#pragma unroll
    for (int c = 0; c < 4; c++) {
        if (c < 3) CP_WAIT(1);
        else       CP_WAIT(0);
        __syncthreads();

        const float* Bf = bufs[c & 1];
        const int m0 = c * 128;
        const int mcol = m0 + w * 8 + 2 * tg;

        // issue S loads early; consumed only in epilogue (overlaps mmas)
        float2 s0 = *(const float2*)&S[sbase + (size_t)g * NNNN + mcol];
        float2 s1 = *(const float2*)&S[sbase + (size_t)(g + 8) * NNNN + mcol];

        float c0 = 0.f, c1 = 0.f, c2 = 0.f, c3 = 0.f;
#pragma unroll
        for (int s = 0; s < 8; s++) {
            unsigned a0 = rwT[g * 68 + s*8 + tg];
            unsigned a1 = rwT[(g + 8) * 68 + s*8 + tg];
            unsigned a2 = rwT[g * 68 + s*8 + 4 + tg];
            unsigned a3 = rwT[(g + 8) * 68 + s*8 + 4 + tg];
            unsigned b0 = f2tf(Bf[(s*8 + tg) * 132 + w * 8 + g]);
            unsigned b1 = f2tf(Bf[(s*8 + 4 + tg) * 132 + w * 8 + g]);
            mma8(c0, c1, c2, c3, a0, a1, a2, a3, b0, b1);
        }
        c0 += rb[g] + s0.x;     c1 += rb[g] + s0.y;
        c2 += rb[g + 8] + s1.x; c3 += rb[g + 8] + s1.y;
        T[mcol * 17 + g]           = c0;
        T[(mcol + 1) * 17 + g]     = c1;
        T[mcol * 17 + g + 8]       = c2;
        T[(mcol + 1) * 17 + g + 8] = c3;
        __syncthreads();

        if (c + 2 < 4) {
            float* dst = bufs[c & 1];
            const int m0n = (c + 2) * 128;
#pragma unroll
            for (int t = tid; t < 2048; t += 512) {
                int e = t >> 5, mf = (t & 31) * 4;
                cpa16(dst + e * 132 + mf, edge + ebase + (size_t)e * NNNN + m0n + mf);
            }
            CP_COMMIT();
        }
    }

    // ---- phase 2: per-head softmax (warp h) ----
    {
        const int h = w;
        float vals[16];
        float mx = -CUDART_INF_F;
#pragma unroll
        for (int i = 0; i < 16; i++) {
            int m = lane + 32 * i;
            vals[i] = T[m * 17 + h];
            if (!mk[m]) mx = fmaxf(mx, vals[i]);
        }
#pragma unroll
        for (int o = 16; o > 0; o >>= 1)
            mx = fmaxf(mx, __shfl_xor_sync(0xffffffffu, mx, o));

        float p[16], sum = 0.f;
#pragma unroll
        for (int i = 0; i < 16; i++) {
            int m = lane + 32 * i;
            p[i] = mk[m] ? 0.f : __expf(vals[i] - mx);
            sum += p[i];
        }
#pragma unroll
        for (int o = 16; o > 0; o >>= 1)
            sum += __shfl_xor_sync(0xffffffffu, sum, o);
        float inv = 1.f / sum;

#pragma unroll
        for (int i = 0; i < 16; i++) {
            int m = lane + 32 * i;
            float a = p[i] * inv;
            S[sbase + (size_t)h * NNNN + m] = a;   // for a@v
            T[m * 17 + h] = a + vals[i];           // residual for edge update
        }
    }
    __syncthreads();

    // ---- phase 3+4: edge expand mma (16-e groups) + write + reduction ----
    {
        unsigned af[2][2][4];
#pragma unroll
        for (int s = 0; s < 2; s++)
#pragma unroll
            for (int i = 0; i < 2; i++) {
                int m = w * 32 + i * 16 + g;
                af[s][i][0] = f2tf(T[m * 17 + s*8 + tg]);
                af[s][i][1] = f2tf(T[(m + 8) * 17 + s*8 + tg]);
                af[s][i][2] = f2tf(T[m * 17 + s*8 + 4 + tg]);
                af[s][i][3] = f2tf(T[(m + 8) * 17 + s*8 + 4 + tg]);
            }

#pragma unroll
        for (int grp = 0; grp < 4; grp++) {
            float acc[2][2][4];
#pragma unroll
            for (int i = 0; i < 2; i++)
#pragma unroll
                for (int jj = 0; jj < 2; jj++)
#pragma unroll
                    for (int q = 0; q < 4; q++) acc[i][jj][q] = 0.f;

#pragma unroll
            for (int s = 0; s < 2; s++)
#pragma unroll
                for (int jj = 0; jj < 2; jj++) {
                    int j = grp * 2 + jj;
                    unsigned b0 = ewT[(s*8 + tg) * 68 + j * 8 + g];
                    unsigned b1 = ewT[(s*8 + 4 + tg) * 68 + j * 8 + g];
                    mma8(acc[0][jj][0], acc[0][jj][1], acc[0][jj][2], acc[0][jj][3],
                         af[s][0][0], af[s][0][1], af[s][0][2], af[s][0][3], b0, b1);
                    mma8(acc[1][jj][0], acc[1][jj][1], acc[1][jj][2], acc[1][jj][3],
                         af[s][1][0], af[s][1][1], af[s][1][2], af[s][1][3], b0, b1);
                }

            float* buf = bufs[grp & 1];
            __syncthreads();
#pragma unroll
            for (int i = 0; i < 2; i++)
#pragma unroll
                for (int jj = 0; jj < 2; jj++) {
                    int m = w * 32 + i * 16 + g;
                    int el = jj * 8 + 2 * tg;
                    int e = grp * 16 + el;
                    buf[el * 516 + m]           = acc[i][jj][0] + eb[e];
                    buf[(el + 1) * 516 + m]     = acc[i][jj][1] + eb[e + 1];
                    buf[el * 516 + m + 8]       = acc[i][jj][2] + eb[e];
                    buf[(el + 1) * 516 + m + 8] = acc[i][jj][3] + eb[e + 1];
                }
            __syncthreads();

            int e = grp * 16 + w;
            float4 v[4];
            float mx = -CUDART_INF_F;
#pragma unroll
            for (int k = 0; k < 4; k++) {
                int m = 4 * lane + 128 * k;
                v[k] = *(float4*)&buf[w * 516 + m];
                __stcs((float4*)&edge_out[ebase + (size_t)e * NNNN + m], v[k]);
                const float* vv = (const float*)&v[k];
#pragma unroll
                for (int cmp = 0; cmp < 4; cmp++)
                    if (!mk[m + cmp]) mx = fmaxf(mx, vv[cmp]);
            }
#pragma unroll
            for (int o = 16; o > 0; o >>= 1)
                mx = fmaxf(mx, __shfl_xor_sync(0xffffffffu, mx, o));

            float sp = 0.f, spv = 0.f;
#pragma unroll
            for (int k = 0; k < 4; k++) {
                int m = 4 * lane + 128 * k;
                const float* vv = (const float*)&v[k];
#pragma unroll
                for (int cmp = 0; cmp < 4; cmp++) {
                    float pp = mk[m + cmp] ? 0.f : __expf(vv[cmp] - mx);
                    sp += pp;
                    spv += pp * vv[cmp];
                }
            }
#pragma unroll
            for (int o = 16; o > 0; o >>= 1) {
                sp  += __shfl_xor_sync(0xffffffffu, sp, o);
                spv += __shfl_xor_sync(0xffffffffu, spv, o);
            }
            if (lane == 0)
                Wg[((size_t)b * NN + n) * EE + e] = spv / sp;
        }
    }
}

// =====================================================================
// x += w @ fc_w^T + fc_b  (K=64)
// =====================================================================
__global__ __launch_bounds__(256) void k_fc(
    const float* __restrict__ Wg, const float* __restrict__ fc_w,
    const float* __restrict__ fc_b, float* __restrict__ x)
{
    __shared__ float ws[64];
    const int bn = blockIdx.x;
    const int tid = threadIdx.x;
    if (tid < 64) ws[tid] = Wg[(size_t)bn * EE + tid];
    __syncthreads();

    for (int c = tid; c < CC; c += 256) {
        float s = fc_b[c];
        const float4* f4 = (const float4*)&fc_w[(size_t)c * EE];
#pragma unroll
        for (int e4 = 0; e4 < 16; e4++) {
            float4 f = f4[e4];
            s += ws[e4*4+0]*f.x + ws[e4*4+1]*f.y + ws[e4*4+2]*f.z + ws[e4*4+3]*f.w;
        }
        x[(size_t)bn * CC + c] += s;
    }
}

// =====================================================================
extern "C" void kernel_launch(void* const* d_in, const int* in_sizes, int n_in,
                              void* d_out, int out_size)
{
    const float*         node     = (const float*)d_in[0];
    const float*         edge     = (const float*)d_in[1];
    const unsigned char* mask     = (const unsigned char*)d_in[2];
    const float*         qkv_w    = (const float*)d_in[3];
    const float*         qkv_b    = (const float*)d_in[4];
    const float*         reduce_w = (const float*)d_in[5];
    const float*         reduce_b = (const float*)d_in[6];
    const float*         expand_w = (const float*)d_in[7];
    const float*         expand_b = (const float*)d_in[8];
    const float*         fc_w     = (const float*)d_in[9];
    const float*         fc_b     = (const float*)d_in[10];
    const float*         proj_w   = (const float*)d_in[11];
    const float*         proj_b   = (const float*)d_in[12];

    float* out_node = (float*)d_out;
    float* out_edge = (float*)d_out + NODE_OUT_ELEMS;

    float *p_qkv, *p_S, *p_W, *p_tmp;
    cudaGetSymbolAddress((void**)&p_qkv, g_qkv);
    cudaGetSymbolAddress((void**)&p_S,   g_S);
    cudaGetSymbolAddress((void**)&p_W,   g_W);
    cudaGetSymbolAddress((void**)&p_tmp, g_tmp);

    cudaFuncSetAttribute(k_fused_mma, cudaFuncAttributeMaxDynamicSharedMemorySize, FUSED_SMEM);
    cudaFuncSetAttribute(k_gemm_mma,  cudaFuncAttributeMaxDynamicSharedMemorySize, GEMM_SMEM);

    // 1. QKV projection: [4096,512] @ [1536,512]^T + b
    k_gemm_mma<<<dim3(12, 32, 1), 256, GEMM_SMEM>>>(node, qkv_w, qkv_b, p_qkv,
        512, 512, 512, 1536, 0, 0, 0, 0, 0, 0, 1.f);

    // 2. scores: per (b,h) Q[512,32] @ K[512,32]^T * SCALE
    k_gemm_mma<<<dim3(4, 4, 128), 256, GEMM_SMEM>>>(p_qkv, p_qkv + 512, nullptr, p_S,
        32, 1536, 1536, 512,
        (size_t)NN*1536, 32, (size_t)NN*1536, 32,
        (size_t)HH*NN*NN, (size_t)NN*NN, SCALE);

    // 3. fused bias + softmax + edge expand + edge reduction
    k_fused_mma<<<dim3(NN, BB), 512, FUSED_SMEM>>>(edge, mask, reduce_w, reduce_b,
        expand_w, expand_b, p_S, out_edge, p_W);

    // 4. node update a @ v
    k_av_mma<<<dim3(4, 128), 128, AV_SMEM>>>(p_S, p_qkv, p_tmp);

    // 5. + w @ fc^T + fc_b
    k_fc<<<BB*NN, 256>>>(p_W, fc_w, fc_b, p_tmp);

    // 6. final projection
    k_gemm_mma<<<dim3(4, 32, 1), 256, GEMM_SMEM>>>(p_tmp, proj_w, proj_b, out_node,
        512, 512, 512, 512, 0, 0, 0, 0, 0, 0, 1.f);
}